// round 2
// baseline (speedup 1.0000x reference)
#include <cuda_runtime.h>

// Inputs (metadata order): x0 [N*D f32], x1 [N*D f32], x_c_0, x_c_1 (unused), y [N i32]
// Output: scalar f32 loss.
//
// loss = sum_i [ y_i * ||x0_i - x1_i||^2 + (1-y_i) * max(0, 1.2 - ||x0_i - x1_i||) ] / (2N)
// (everything else in the reference is dead code w.r.t. the returned value)

#define NBLOCKS 1216   // 152 SMs * 8 resident CTAs -> single persistent wave

__global__ void zero_out_kernel(float* out) {
    if (threadIdx.x == 0) out[0] = 0.0f;
}

__global__ __launch_bounds__(256, 8)
void direction_loss_kernel(const float4* __restrict__ x0,
                           const float4* __restrict__ x1,
                           const int* __restrict__ y,
                           float* __restrict__ out,
                           int N,
                           int Dvec,          // D / 4
                           float inv_2N)      // 1 / (2N)
{
    __shared__ float wsum[8];
    const int lane = threadIdx.x & 31;
    const int wid  = threadIdx.x >> 5;

    float local_loss = 0.0f;   // meaningful on (wid==0, lane==0) only

    for (int row = blockIdx.x; row < N; row += NBLOCKS) {
        const size_t base = (size_t)row * (size_t)Dvec;
        const float4* a = x0 + base;
        const float4* b = x1 + base;

        float s = 0.0f;
        // Dvec = 1024, 256 threads -> 4 iterations; full unroll front-batches
        // 8 independent LDG.128 per thread.
        #pragma unroll 4
        for (int i = threadIdx.x; i < Dvec; i += 256) {
            float4 av = a[i];
            float4 bv = b[i];
            float dx = av.x - bv.x;
            float dy = av.y - bv.y;
            float dz = av.z - bv.z;
            float dw = av.w - bv.w;
            s = fmaf(dx, dx, s);
            s = fmaf(dy, dy, s);
            s = fmaf(dz, dz, s);
            s = fmaf(dw, dw, s);
        }

        // Warp reduce
        #pragma unroll
        for (int o = 16; o > 0; o >>= 1)
            s += __shfl_xor_sync(0xffffffffu, s, o);

        if (lane == 0) wsum[wid] = s;
        __syncthreads();

        if (wid == 0) {
            s = (lane < 8) ? wsum[lane] : 0.0f;
            #pragma unroll
            for (int o = 4; o > 0; o >>= 1)
                s += __shfl_xor_sync(0xffffffffu, s, o);
            if (lane == 0) {
                const float yf = (float)y[row];
                const float e_dist = sqrtf(s);
                const float e_clamped = fmaxf(1.2f - e_dist, 0.0f);
                local_loss += yf * s + (1.0f - yf) * e_clamped;
            }
        }
        __syncthreads();   // protect wsum reuse next iteration
    }

    if (wid == 0 && lane == 0 && local_loss != 0.0f)
        atomicAdd(out, local_loss * inv_2N);
    else if (wid == 0 && lane == 0)
        ;  // nothing to add
}

extern "C" void kernel_launch(void* const* d_in, const int* in_sizes, int n_in,
                              void* d_out, int out_size) {
    const float* x0 = (const float*)d_in[0];
    const float* x1 = (const float*)d_in[1];
    const int*   y  = (const int*)d_in[4];
    float* out = (float*)d_out;

    const int N = in_sizes[4];          // 4096
    const int D = in_sizes[0] / N;      // 4096
    const int Dvec = D / 4;             // 1024
    const float inv_2N = 0.5f / (float)N;

    zero_out_kernel<<<1, 32>>>(out);
    direction_loss_kernel<<<NBLOCKS, 256>>>((const float4*)x0, (const float4*)x1,
                                            y, out, N, Dvec, inv_2N);
}

// round 3
// speedup vs baseline: 1.0585x; 1.0585x over previous
#include <cuda_runtime.h>

// Inputs (metadata order): x0 [N*D f32], x1 [N*D f32], x_c_0, x_c_1 (unused), y [N i32]
// Output: scalar f32 loss.
//
// loss = sum_i [ y_i * ||x0_i - x1_i||^2 + (1-y_i) * max(0, 1.2 - ||x0_i - x1_i||) ] / (2N)
// (everything else in the reference is dead code w.r.t. the returned value)

#define MAX_N 8192

__device__ float        g_row_loss[MAX_N];
__device__ unsigned int g_done_count = 0;   // reset to 0 by the last block each run

__global__ __launch_bounds__(256, 8)
void direction_loss_kernel(const float4* __restrict__ x0,
                           const float4* __restrict__ x1,
                           const int* __restrict__ y,
                           float* __restrict__ out,
                           int N,
                           int Dvec,          // D / 4
                           float inv_2N)      // 1 / (2N)
{
    const int row  = blockIdx.x;
    const int lane = threadIdx.x & 31;
    const int wid  = threadIdx.x >> 5;

    // Hoist label load (broadcast, L1-hit) so the tail math has no load dep.
    const float yf = (float)y[row];

    const size_t base = (size_t)row * (size_t)Dvec;
    const float4* a = x0 + base;
    const float4* b = x1 + base;

    float s = 0.0f;
    // Dvec = 1024, 256 threads -> 4 iterations; full unroll front-batches
    // 8 independent LDG.128 per thread.
    #pragma unroll 4
    for (int i = threadIdx.x; i < Dvec; i += 256) {
        float4 av = a[i];
        float4 bv = b[i];
        float dx = av.x - bv.x;
        float dy = av.y - bv.y;
        float dz = av.z - bv.z;
        float dw = av.w - bv.w;
        s = fmaf(dx, dx, s);
        s = fmaf(dy, dy, s);
        s = fmaf(dz, dz, s);
        s = fmaf(dw, dw, s);
    }

    // Warp reduce
    #pragma unroll
    for (int o = 16; o > 0; o >>= 1)
        s += __shfl_xor_sync(0xffffffffu, s, o);

    __shared__ float wsum[8];
    __shared__ bool  is_last;
    if (lane == 0) wsum[wid] = s;
    __syncthreads();

    if (wid == 0) {
        s = (lane < 8) ? wsum[lane] : 0.0f;
        #pragma unroll
        for (int o = 4; o > 0; o >>= 1)
            s += __shfl_xor_sync(0xffffffffu, s, o);
        if (lane == 0) {
            const float e_dist    = sqrtf(s);
            const float e_clamped = fmaxf(1.2f - e_dist, 0.0f);
            g_row_loss[row] = yf * s + (1.0f - yf) * e_clamped;
            __threadfence();
            unsigned int old = atomicAdd(&g_done_count, 1u);
            is_last = (old == (unsigned int)(gridDim.x - 1));
        }
    }
    __syncthreads();

    // Last block to finish reduces all per-row terms and writes the scalar.
    if (is_last) {
        __threadfence();   // acquire: make all g_row_loss stores visible
        float t = 0.0f;
        for (int i = threadIdx.x; i < N; i += 256)
            t += g_row_loss[i];

        #pragma unroll
        for (int o = 16; o > 0; o >>= 1)
            t += __shfl_xor_sync(0xffffffffu, t, o);

        if (lane == 0) wsum[wid] = t;
        __syncthreads();

        if (wid == 0) {
            t = (lane < 8) ? wsum[lane] : 0.0f;
            #pragma unroll
            for (int o = 4; o > 0; o >>= 1)
                t += __shfl_xor_sync(0xffffffffu, t, o);
            if (lane == 0) {
                out[0] = t * inv_2N;
                g_done_count = 0;   // restore state for the next graph replay
            }
        }
    }
}

extern "C" void kernel_launch(void* const* d_in, const int* in_sizes, int n_in,
                              void* d_out, int out_size) {
    const float* x0 = (const float*)d_in[0];
    const float* x1 = (const float*)d_in[1];
    const int*   y  = (const int*)d_in[4];
    float* out = (float*)d_out;

    const int N = in_sizes[4];          // 4096
    const int D = in_sizes[0] / N;      // 4096
    const int Dvec = D / 4;             // 1024
    const float inv_2N = 0.5f / (float)N;

    direction_loss_kernel<<<N, 256>>>((const float4*)x0, (const float4*)x1,
                                      y, out, N, Dvec, inv_2N);
}